// round 2
// baseline (speedup 1.0000x reference)
#include <cuda_runtime.h>
#include <cuda_bf16.h>
#include <cstdint>

// x: (16, 64, 256, 256) fp32 -> 64 Mi elements. 65536 floats per channel.
// posIdx: 64 ints (bool serialized as int32 by the harness).
// out = posIdx[c] ? relu(x) : x
//
// Memory-bound: 512 MB total traffic. One float4 per thread.
// vec4s per channel = 65536/4 = 16384 = 2^14  ->  c = (v >> 14) & 63

__global__ void __launch_bounds__(256) partial_relu_kernel(
    const float4* __restrict__ x,
    const int* __restrict__ posIdx,
    float4* __restrict__ out)
{
    unsigned int v = blockIdx.x * 256u + threadIdx.x;   // 0 .. 16M-1, grid sized exactly
    unsigned int c = (v >> 14) & 63u;
    bool m = posIdx[c] != 0;   // broadcast int32 load, L1-cached

    float4 val = x[v];
    if (m) {
        val.x = fmaxf(val.x, 0.0f);
        val.y = fmaxf(val.y, 0.0f);
        val.z = fmaxf(val.z, 0.0f);
        val.w = fmaxf(val.w, 0.0f);
    }
    out[v] = val;
}

extern "C" void kernel_launch(void* const* d_in, const int* in_sizes, int n_in,
                              void* d_out, int out_size)
{
    const float4* x = (const float4*)d_in[0];
    const int* posIdx = (const int*)d_in[1];
    float4* out = (float4*)d_out;

    // total elements = 16*64*256*256 = 67108864 -> 16777216 vec4
    const unsigned int nvec = 16777216u;
    const unsigned int threads = 256u;
    const unsigned int blocks = nvec / threads;  // 65536
    partial_relu_kernel<<<blocks, threads>>>(x, posIdx, out);
}

// round 4
// speedup vs baseline: 1.0023x; 1.0023x over previous
#include <cuda_runtime.h>
#include <cuda_bf16.h>
#include <cstdint>

// x: (16, 64, 256, 256) fp32 = 64 Mi elements = 16 Mi float4.
// posIdx: 64 int32 (bool serialized as int32).
// out = posIdx[c] ? relu(x) : x
//
// 16384 vec4 per channel. Each block covers 4*256 = 1024 contiguous vec4,
// and 16384 % 1024 == 0, so every block lies within ONE channel:
//   channel(block) = (blockIdx.x >> 4) & 63
// Mask is block-uniform -> single scalar load, zero per-thread index math.
//
// MLP=4: four independent LDG.128 issued before any store.

__global__ void __launch_bounds__(256) partial_relu_kernel(
    const float4* __restrict__ x,
    const int* __restrict__ posIdx,
    float4* __restrict__ out)
{
    const unsigned int base = blockIdx.x * 1024u + threadIdx.x;  // first of 4 vec4
    const bool m = posIdx[(blockIdx.x >> 4) & 63u] != 0;         // uniform per block

    float4 v0 = __ldcs(&x[base]);
    float4 v1 = __ldcs(&x[base + 256u]);
    float4 v2 = __ldcs(&x[base + 512u]);
    float4 v3 = __ldcs(&x[base + 768u]);

    if (m) {
        v0.x = fmaxf(v0.x, 0.0f); v0.y = fmaxf(v0.y, 0.0f);
        v0.z = fmaxf(v0.z, 0.0f); v0.w = fmaxf(v0.w, 0.0f);
        v1.x = fmaxf(v1.x, 0.0f); v1.y = fmaxf(v1.y, 0.0f);
        v1.z = fmaxf(v1.z, 0.0f); v1.w = fmaxf(v1.w, 0.0f);
        v2.x = fmaxf(v2.x, 0.0f); v2.y = fmaxf(v2.y, 0.0f);
        v2.z = fmaxf(v2.z, 0.0f); v2.w = fmaxf(v2.w, 0.0f);
        v3.x = fmaxf(v3.x, 0.0f); v3.y = fmaxf(v3.y, 0.0f);
        v3.z = fmaxf(v3.z, 0.0f); v3.w = fmaxf(v3.w, 0.0f);
    }

    __stcs(&out[base],        v0);
    __stcs(&out[base + 256u], v1);
    __stcs(&out[base + 512u], v2);
    __stcs(&out[base + 768u], v3);
}

extern "C" void kernel_launch(void* const* d_in, const int* in_sizes, int n_in,
                              void* d_out, int out_size)
{
    const float4* x = (const float4*)d_in[0];
    const int* posIdx = (const int*)d_in[1];
    float4* out = (float4*)d_out;

    // 16777216 vec4 total / (1024 vec4 per block) = 16384 blocks
    partial_relu_kernel<<<16384, 256>>>(x, posIdx, out);
}